// round 16
// baseline (speedup 1.0000x reference)
#include <cuda_runtime.h>
#include <cuda_bf16.h>
#include <cuda_fp16.h>
#include <cstdint>

#define N_NODES 50000
#define N_EDGES 1250000
#define HID 64
#define CDIM 128
#define NTILE 32                                     // K1 GEMM tile
#define N_TILES ((N_NODES + NTILE - 1) / NTILE)
#define SCAT_BLOCKS 444
#define GEMM_BLOCKS 148
#define TOTAL_BLOCKS (SCAT_BLOCKS + GEMM_BLOCKS)
#define TOTAL_ITEMS (16LL * N_EDGES)
#define SPLIT_ITEMS 17500000LL

#define MT 128                                       // mlp2 nodes per block
#define M_BLOCKS ((N_NODES + MT - 1) / MT)           // 391
#define APH 20      // act row pad (uint2)
#define WPH 20      // weight row pad (uint2)

// scratch: t1 = x @ W1[0:64] + b1  (fp32, computed free inside K1)
__device__ float d_t1[(size_t)N_NODES * HID];

// ---------------------------------------------------------------------------
// helpers
// ---------------------------------------------------------------------------
__device__ __forceinline__ uint32_t h2bits(float lo, float hi) {
    __half2 h = __floats2half2_rn(lo, hi);
    return *(uint32_t*)&h;
}

__device__ __forceinline__ void mma_f16(float& d0, float& d1, float& d2, float& d3,
                                        uint32_t a0, uint32_t a1, uint32_t a2, uint32_t a3,
                                        uint32_t b0, uint32_t b1) {
    asm("mma.sync.aligned.m16n8k16.row.col.f32.f16.f16.f32 "
        "{%0,%1,%2,%3}, {%4,%5,%6,%7}, {%8,%9}, {%0,%1,%2,%3};"
        : "+f"(d0), "+f"(d1), "+f"(d2), "+f"(d3)
        : "r"(a0), "r"(a1), "r"(a2), "r"(a3), "r"(b0), "r"(b1));
}

// ---------------------------------------------------------------------------
// scatter: sequential edge_attr stream + v4 reductions (proven)
// ---------------------------------------------------------------------------
__device__ __forceinline__ void scatter_range(const int* __restrict__ row,
                                              const float4* __restrict__ attr4,
                                              float* __restrict__ combined,
                                              long long beg, long long end,
                                              long long idx0, long long stride) {
    int lane = threadIdx.x & 31;
    int g = (int)((beg + idx0) & 15);
    long long idx = beg + idx0;

    while (idx - lane + 31 < end) {
        int e = (int)(idx >> 4);
        int r;
        if ((lane & 15) == 0) r = __ldg(row + e);
        r = __shfl_sync(0xffffffffu, r, lane & 16);
        float4 v = __ldg(attr4 + idx);
        float* dst = combined + (size_t)r * CDIM + HID + g * 4;
        asm volatile("red.global.add.v4.f32 [%0], {%1, %2, %3, %4};"
                     :: "l"(dst), "f"(v.x), "f"(v.y), "f"(v.z), "f"(v.w)
                     : "memory");
        idx += stride;
    }
    if (idx < end) {
        int e = (int)(idx >> 4);
        int r = __ldg(row + e);
        float4 v = __ldg(attr4 + idx);
        float* dst = combined + (size_t)r * CDIM + HID + g * 4;
        asm volatile("red.global.add.v4.f32 [%0], {%1, %2, %3, %4};"
                     :: "l"(dst), "f"(v.x), "f"(v.y), "f"(v.z), "f"(v.w)
                     : "memory");
    }
}

// ---------------------------------------------------------------------------
// K1: fused scatter + t1-GEMM (+ combined[:,0:64] = x copy)  (proven)
// ---------------------------------------------------------------------------
__global__ void scatter_gemm_kernel(const int* __restrict__ row,
                                    const float4* __restrict__ attr4,
                                    const float4* __restrict__ x4,
                                    const float* __restrict__ W1,
                                    const float* __restrict__ b1,
                                    float* __restrict__ combined) {
    int tid = threadIdx.x;

    if (blockIdx.x < SCAT_BLOCKS) {
        long long idx0 = (long long)blockIdx.x * 256 + tid;
        scatter_range(row, attr4, combined, 0, SPLIT_ITEMS,
                      idx0, (long long)SCAT_BLOCKS * 256);
        return;
    }

    extern __shared__ float4 smem4[];
    float*  sW  = (float*)smem4;
    float4* sx4 = smem4 + (HID * HID) / 4;

    for (int i = tid; i < HID * HID; i += 256) sW[i] = W1[i];
    float bj = __ldg(b1 + (tid & 63));
    __syncthreads();

    int g = tid >> 6;
    int j = tid & 63;
    int bid = blockIdx.x - SCAT_BLOCKS;
    float4* comb4 = (float4*)combined;

    for (int tile = bid; tile < N_TILES; tile += GEMM_BLOCKS) {
        int node0 = tile * NTILE;
        for (int i = tid; i < NTILE * 16; i += 256) {
            int n = node0 + (i >> 4), q = i & 15;
            float4 v = make_float4(0.f, 0.f, 0.f, 0.f);
            if (n < N_NODES) {
                v = __ldg(x4 + (size_t)n * 16 + q);
                comb4[(size_t)n * 32 + q] = v;
            }
            sx4[i] = v;
        }
        __syncthreads();

        float acc[8];
        #pragma unroll
        for (int n = 0; n < 8; n++) acc[n] = bj;

        const float4* c0 = sx4 + g * 8 * 16;
        #pragma unroll 4
        for (int i4 = 0; i4 < 16; i4++) {
            float w0 = sW[(i4 * 4 + 0) * HID + j];
            float w1 = sW[(i4 * 4 + 1) * HID + j];
            float w2 = sW[(i4 * 4 + 2) * HID + j];
            float w3 = sW[(i4 * 4 + 3) * HID + j];
            #pragma unroll
            for (int n = 0; n < 8; n++) {
                float4 c = c0[n * 16 + i4];
                acc[n] = fmaf(c.x, w0, acc[n]);
                acc[n] = fmaf(c.y, w1, acc[n]);
                acc[n] = fmaf(c.z, w2, acc[n]);
                acc[n] = fmaf(c.w, w3, acc[n]);
            }
        }
        #pragma unroll
        for (int n = 0; n < 8; n++) {
            int node = node0 + g * 8 + n;
            if (node < N_NODES) d_t1[(size_t)node * HID + j] = acc[n];
        }
        __syncthreads();
    }

    long long idx0 = (long long)bid * 256 + tid;
    scatter_range(row, attr4, combined, SPLIT_ITEMS, TOTAL_ITEMS,
                  idx0, (long long)GEMM_BLOCKS * 256);
}

// ---------------------------------------------------------------------------
// K2 (tensor): out = silu(t1 + agg @ W1b) @ W2 + b2   via mma.sync fp16 k16.
// (R15 formulation, proven.)
// ---------------------------------------------------------------------------
__global__ void __launch_bounds__(256, 4)
mlp2_mma_kernel(const float* __restrict__ combined,
                const float* __restrict__ W1,
                const float* __restrict__ W2,
                const float* __restrict__ b2,
                float* __restrict__ out) {
    extern __shared__ uint2 smem_p[];
    uint2* sW1p = smem_p;                        // [64][WPH]
    uint2* sW2p = sW1p + HID * WPH;              // [64][WPH]
    uint2* sAp  = sW2p + HID * WPH;              // [128][APH] (agg, then h)

    int tid  = threadIdx.x;
    int wid  = tid >> 5;
    int lane = tid & 31;
    int g = lane >> 2;
    int t = lane & 3;
    int node0 = blockIdx.x * MT;

    // ---- stage weights: item = (kt, tt, n-quad) ----
    #pragma unroll
    for (int i = tid; i < 256; i += 256) {       // exactly one item/thread
        int kt = i >> 6, tt = (i >> 4) & 3, n0 = (i & 15) * 4;
        int k0 = kt * 16 + 2 * tt;
        float4 wa = __ldg((const float4*)(W1 + (size_t)(HID + k0)     * HID + n0));
        float4 wb = __ldg((const float4*)(W1 + (size_t)(HID + k0 + 1) * HID + n0));
        float4 wc = __ldg((const float4*)(W1 + (size_t)(HID + k0 + 8) * HID + n0));
        float4 wd = __ldg((const float4*)(W1 + (size_t)(HID + k0 + 9) * HID + n0));
        float4 va = __ldg((const float4*)(W2 + (size_t)k0       * HID + n0));
        float4 vb = __ldg((const float4*)(W2 + (size_t)(k0 + 1) * HID + n0));
        float4 vc = __ldg((const float4*)(W2 + (size_t)(k0 + 8) * HID + n0));
        float4 vd = __ldg((const float4*)(W2 + (size_t)(k0 + 9) * HID + n0));
        int slot = kt * 4 + tt;
        #pragma unroll
        for (int n = 0; n < 4; n++) {
            float a0 = (&wa.x)[n], b0 = (&wb.x)[n], c0 = (&wc.x)[n], d0 = (&wd.x)[n];
            float a2 = (&va.x)[n], b2v = (&vb.x)[n], c2 = (&vc.x)[n], d2 = (&vd.x)[n];
            sW1p[(n0 + n) * WPH + slot] = make_uint2(h2bits(a0, b0), h2bits(c0, d0));
            sW2p[(n0 + n) * WPH + slot] = make_uint2(h2bits(a2, b2v), h2bits(c2, d2));
        }
    }

    // ---- stage agg: item = (node, kt): 16 floats -> 8 kpairs -> 4 uint2 ----
    const float4* comb4 = (const float4*)combined;
    #pragma unroll
    for (int i = tid; i < MT * 4; i += 256) {
        int n = i >> 2, kt = i & 3;
        int node = node0 + n;
        float4 f0 = make_float4(0.f,0.f,0.f,0.f), f1 = f0, f2 = f0, f3 = f0;
        if (node < N_NODES) {
            const float4* src = comb4 + (size_t)node * 32 + 16 + kt * 4;
            f0 = __ldg(src + 0); f1 = __ldg(src + 1);
            f2 = __ldg(src + 2); f3 = __ldg(src + 3);
        }
        uint32_t p0 = h2bits(f0.x, f0.y), p1 = h2bits(f0.z, f0.w);
        uint32_t p2 = h2bits(f1.x, f1.y), p3 = h2bits(f1.z, f1.w);
        uint32_t p4 = h2bits(f2.x, f2.y), p5 = h2bits(f2.z, f2.w);
        uint32_t p6 = h2bits(f3.x, f3.y), p7 = h2bits(f3.z, f3.w);
        uint4* dst = (uint4*)(sAp + n * APH + kt * 4);
        dst[0] = make_uint4(p0, p4, p1, p5);
        dst[1] = make_uint4(p2, p6, p3, p7);
    }

    int m0 = wid * 16;                 // warp's rows within the tile
    int rowA = node0 + m0 + g;         // frag rows (g)
    int rowB = rowA + 8;               // (g+8)
    bool okA = rowA < N_NODES;
    bool okB = rowB < N_NODES;

    // ---- layer 1 accumulators: D = t1 + agg @ W1b ----
    float d[8][4];
    #pragma unroll
    for (int nt = 0; nt < 8; nt++) {
        float2 vA = make_float2(0.f, 0.f), vB = make_float2(0.f, 0.f);
        if (okA) vA = *(const float2*)(d_t1 + (size_t)rowA * HID + nt * 8 + 2 * t);
        if (okB) vB = *(const float2*)(d_t1 + (size_t)rowB * HID + nt * 8 + 2 * t);
        d[nt][0] = vA.x; d[nt][1] = vA.y; d[nt][2] = vB.x; d[nt][3] = vB.y;
    }
    __syncthreads();

    // ---- layer 1 mainloop (4 kt-steps of K=16) ----
    #pragma unroll
    for (int kt = 0; kt < 4; kt++) {
        uint2 pA0 = sAp[(m0 + g)     * APH + kt * 4 + t];   // {a0, a2}
        uint2 pA1 = sAp[(m0 + g + 8) * APH + kt * 4 + t];   // {a1, a3}
        #pragma unroll
        for (int nt = 0; nt < 8; nt++) {
            uint2 b = sW1p[(nt * 8 + g) * WPH + kt * 4 + t];
            mma_f16(d[nt][0], d[nt][1], d[nt][2], d[nt][3],
                    pA0.x, pA1.x, pA0.y, pA1.y, b.x, b.y);
        }
    }
    __syncwarp();   // warp-private sAp rows: all layer-1 reads done

    // ---- SiLU; store h into warp's own sAp rows ----
    #pragma unroll
    for (int nt = 0; nt < 8; nt++) {
        float h0 = __fdividef(d[nt][0], 1.0f + __expf(-d[nt][0]));
        float h1 = __fdividef(d[nt][1], 1.0f + __expf(-d[nt][1]));
        float h2 = __fdividef(d[nt][2], 1.0f + __expf(-d[nt][2]));
        float h3 = __fdividef(d[nt][3], 1.0f + __expf(-d[nt][3]));
        int q = nt * 4 + t;
        int kt_h = q >> 3, r = q & 7;
        int word = 2 * (kt_h * 4 + (r & 3)) + (r >> 2);
        ((uint32_t*)(sAp + (m0 + g)     * APH))[word] = h2bits(h0, h1);
        ((uint32_t*)(sAp + (m0 + g + 8) * APH))[word] = h2bits(h2, h3);
    }
    __syncwarp();

    // ---- layer 2: D = b2 + h @ W2 ----
    #pragma unroll
    for (int nt = 0; nt < 8; nt++) {
        float2 bb = *(const float2*)(b2 + nt * 8 + 2 * t);
        d[nt][0] = bb.x; d[nt][1] = bb.y; d[nt][2] = bb.x; d[nt][3] = bb.y;
    }

    #pragma unroll
    for (int kt = 0; kt < 4; kt++) {
        uint2 pA0 = sAp[(m0 + g)     * APH + kt * 4 + t];
        uint2 pA1 = sAp[(m0 + g + 8) * APH + kt * 4 + t];
        #pragma unroll
        for (int nt = 0; nt < 8; nt++) {
            uint2 b = sW2p[(nt * 8 + g) * WPH + kt * 4 + t];
            mma_f16(d[nt][0], d[nt][1], d[nt][2], d[nt][3],
                    pA0.x, pA1.x, pA0.y, pA1.y, b.x, b.y);
        }
    }

    // ---- write out ----
    #pragma unroll
    for (int nt = 0; nt < 8; nt++) {
        if (okA) {
            *(float2*)(out + (size_t)rowA * HID + nt * 8 + 2 * t)
                = make_float2(d[nt][0], d[nt][1]);
        }
        if (okB) {
            *(float2*)(out + (size_t)rowB * HID + nt * 8 + 2 * t)
                = make_float2(d[nt][2], d[nt][3]);
        }
    }
}

// ---------------------------------------------------------------------------
extern "C" void kernel_launch(void* const* d_in, const int* in_sizes, int n_in,
                              void* d_out, int out_size) {
    const int*   edge_index = (const int*)d_in[0];
    const float* edge_attr  = (const float*)d_in[1];
    const float* x          = (const float*)d_in[2];
    const float* W1         = (const float*)d_in[3];
    const float* b1         = (const float*)d_in[4];
    const float* W2         = (const float*)d_in[5];
    const float* b2         = (const float*)d_in[6];

    float* out      = (float*)d_out;
    float* combined = out + (size_t)N_NODES * HID;

    // zero ONLY the agg half (columns 64:128) via pitched memset — the x half
    // is overwritten by K1's GEMM branch.
    cudaMemset2DAsync(combined + HID, CDIM * sizeof(float), 0,
                      HID * sizeof(float), N_NODES);

    // K1: scatter + t1 GEMM + x copy
    {
        int smem = (HID * HID) * 4 + NTILE * 16 * 16;
        cudaFuncSetAttribute(scatter_gemm_kernel,
                             cudaFuncAttributeMaxDynamicSharedMemorySize, smem);
        scatter_gemm_kernel<<<TOTAL_BLOCKS, 256, smem>>>(
            edge_index, (const float4*)edge_attr, (const float4*)x,
            W1, b1, combined);
    }

    // K2: tensor-core MLP (fp16 k16), max shared carveout for occupancy
    {
        int smem = (2 * HID * WPH + MT * APH) * (int)sizeof(uint2);   // 40 KB
        cudaFuncSetAttribute(mlp2_mma_kernel,
                             cudaFuncAttributeMaxDynamicSharedMemorySize, smem);
        cudaFuncSetAttribute(mlp2_mma_kernel,
                             cudaFuncAttributePreferredSharedMemoryCarveout, 100);
        mlp2_mma_kernel<<<M_BLOCKS, 256, smem>>>(combined, W1, W2, b2, out);
    }
}

// round 17
// speedup vs baseline: 1.1645x; 1.1645x over previous
#include <cuda_runtime.h>
#include <cuda_bf16.h>
#include <cuda_fp16.h>
#include <cstdint>

#define N_NODES 50000
#define N_EDGES 1250000
#define HID 64
#define CDIM 128
#define NTILE 32                                     // K1 GEMM tile
#define N_TILES ((N_NODES + NTILE - 1) / NTILE)
#define SCAT_BLOCKS 444
#define GEMM_BLOCKS 148
#define TOTAL_BLOCKS (SCAT_BLOCKS + GEMM_BLOCKS)
#define TOTAL_ITEMS (16LL * N_EDGES)
#define SPLIT_ITEMS 17500000LL

#define MT 128                                       // mlp2 nodes per block
#define M_BLOCKS ((N_NODES + MT - 1) / MT)           // 391
#define APH 20      // act row pad (uint2)
#define WPH 20      // weight row pad (uint2)

// scratch: t1 = x @ W1[0:64] + b1  (fp32, computed free inside K1)
__device__ float d_t1[(size_t)N_NODES * HID];

// ---------------------------------------------------------------------------
// helpers
// ---------------------------------------------------------------------------
__device__ __forceinline__ uint32_t h2bits(float lo, float hi) {
    __half2 h = __floats2half2_rn(lo, hi);
    return *(uint32_t*)&h;
}

__device__ __forceinline__ void mma_f16(float& d0, float& d1, float& d2, float& d3,
                                        uint32_t a0, uint32_t a1, uint32_t a2, uint32_t a3,
                                        uint32_t b0, uint32_t b1) {
    asm("mma.sync.aligned.m16n8k16.row.col.f32.f16.f16.f32 "
        "{%0,%1,%2,%3}, {%4,%5,%6,%7}, {%8,%9}, {%0,%1,%2,%3};"
        : "+f"(d0), "+f"(d1), "+f"(d2), "+f"(d3)
        : "r"(a0), "r"(a1), "r"(a2), "r"(a3), "r"(b0), "r"(b1));
}

// ---------------------------------------------------------------------------
// scatter: sequential edge_attr stream + v4 reductions (proven)
// ---------------------------------------------------------------------------
__device__ __forceinline__ void scatter_range(const int* __restrict__ row,
                                              const float4* __restrict__ attr4,
                                              float* __restrict__ combined,
                                              long long beg, long long end,
                                              long long idx0, long long stride) {
    int lane = threadIdx.x & 31;
    int g = (int)((beg + idx0) & 15);
    long long idx = beg + idx0;

    while (idx - lane + 31 < end) {
        int e = (int)(idx >> 4);
        int r;
        if ((lane & 15) == 0) r = __ldg(row + e);
        r = __shfl_sync(0xffffffffu, r, lane & 16);
        float4 v = __ldg(attr4 + idx);
        float* dst = combined + (size_t)r * CDIM + HID + g * 4;
        asm volatile("red.global.add.v4.f32 [%0], {%1, %2, %3, %4};"
                     :: "l"(dst), "f"(v.x), "f"(v.y), "f"(v.z), "f"(v.w)
                     : "memory");
        idx += stride;
    }
    if (idx < end) {
        int e = (int)(idx >> 4);
        int r = __ldg(row + e);
        float4 v = __ldg(attr4 + idx);
        float* dst = combined + (size_t)r * CDIM + HID + g * 4;
        asm volatile("red.global.add.v4.f32 [%0], {%1, %2, %3, %4};"
                     :: "l"(dst), "f"(v.x), "f"(v.y), "f"(v.z), "f"(v.w)
                     : "memory");
    }
}

// ---------------------------------------------------------------------------
// K1: fused scatter + t1-GEMM (+ combined[:,0:64] = x copy)  (proven)
// ---------------------------------------------------------------------------
__global__ void scatter_gemm_kernel(const int* __restrict__ row,
                                    const float4* __restrict__ attr4,
                                    const float4* __restrict__ x4,
                                    const float* __restrict__ W1,
                                    const float* __restrict__ b1,
                                    float* __restrict__ combined) {
    int tid = threadIdx.x;

    if (blockIdx.x < SCAT_BLOCKS) {
        long long idx0 = (long long)blockIdx.x * 256 + tid;
        scatter_range(row, attr4, combined, 0, SPLIT_ITEMS,
                      idx0, (long long)SCAT_BLOCKS * 256);
        return;
    }

    extern __shared__ float4 smem4[];
    float*  sW  = (float*)smem4;
    float4* sx4 = smem4 + (HID * HID) / 4;

    for (int i = tid; i < HID * HID; i += 256) sW[i] = W1[i];
    float bj = __ldg(b1 + (tid & 63));
    __syncthreads();

    int g = tid >> 6;
    int j = tid & 63;
    int bid = blockIdx.x - SCAT_BLOCKS;
    float4* comb4 = (float4*)combined;

    for (int tile = bid; tile < N_TILES; tile += GEMM_BLOCKS) {
        int node0 = tile * NTILE;
        for (int i = tid; i < NTILE * 16; i += 256) {
            int n = node0 + (i >> 4), q = i & 15;
            float4 v = make_float4(0.f, 0.f, 0.f, 0.f);
            if (n < N_NODES) {
                v = __ldg(x4 + (size_t)n * 16 + q);
                comb4[(size_t)n * 32 + q] = v;
            }
            sx4[i] = v;
        }
        __syncthreads();

        float acc[8];
        #pragma unroll
        for (int n = 0; n < 8; n++) acc[n] = bj;

        const float4* c0 = sx4 + g * 8 * 16;
        #pragma unroll 4
        for (int i4 = 0; i4 < 16; i4++) {
            float w0 = sW[(i4 * 4 + 0) * HID + j];
            float w1 = sW[(i4 * 4 + 1) * HID + j];
            float w2 = sW[(i4 * 4 + 2) * HID + j];
            float w3 = sW[(i4 * 4 + 3) * HID + j];
            #pragma unroll
            for (int n = 0; n < 8; n++) {
                float4 c = c0[n * 16 + i4];
                acc[n] = fmaf(c.x, w0, acc[n]);
                acc[n] = fmaf(c.y, w1, acc[n]);
                acc[n] = fmaf(c.z, w2, acc[n]);
                acc[n] = fmaf(c.w, w3, acc[n]);
            }
        }
        #pragma unroll
        for (int n = 0; n < 8; n++) {
            int node = node0 + g * 8 + n;
            if (node < N_NODES) d_t1[(size_t)node * HID + j] = acc[n];
        }
        __syncthreads();
    }

    long long idx0 = (long long)bid * 256 + tid;
    scatter_range(row, attr4, combined, SPLIT_ITEMS, TOTAL_ITEMS,
                  idx0, (long long)GEMM_BLOCKS * 256);
}

// ---------------------------------------------------------------------------
// K2 (tensor): out = silu(t1 + agg @ W1b) @ W2 + b2   via mma.sync fp16 k16.
// 512 threads = 16 warps; warp (wm, wn): rows [wm*16, wm*16+16), output cols
// [wn*32, wn*32+32) (4 nt). 2x warps vs R15 for the latency-bound regime;
// h handoff is cross-warp -> block syncs around the SiLU store.
// ---------------------------------------------------------------------------
__global__ void __launch_bounds__(512, 2)
mlp2_mma_kernel(const float* __restrict__ combined,
                const float* __restrict__ W1,
                const float* __restrict__ W2,
                const float* __restrict__ b2,
                float* __restrict__ out) {
    extern __shared__ uint2 smem_p[];
    uint2* sW1p = smem_p;                        // [64][WPH]
    uint2* sW2p = sW1p + HID * WPH;              // [64][WPH]
    uint2* sAp  = sW2p + HID * WPH;              // [128][APH] (agg, then h)

    int tid  = threadIdx.x;
    int wid  = tid >> 5;
    int lane = tid & 31;
    int g = lane >> 2;
    int t = lane & 3;
    int wm = wid >> 1;          // row group 0..7
    int wn = wid & 1;           // col half 0..1
    int node0 = blockIdx.x * MT;

    // ---- stage weights: item = (kt, tt, n-quad); 256 items, 512 threads ----
    if (tid < 256) {
        int i = tid;
        int kt = i >> 6, tt = (i >> 4) & 3, n0 = (i & 15) * 4;
        int k0 = kt * 16 + 2 * tt;
        float4 wa = __ldg((const float4*)(W1 + (size_t)(HID + k0)     * HID + n0));
        float4 wb = __ldg((const float4*)(W1 + (size_t)(HID + k0 + 1) * HID + n0));
        float4 wc = __ldg((const float4*)(W1 + (size_t)(HID + k0 + 8) * HID + n0));
        float4 wd = __ldg((const float4*)(W1 + (size_t)(HID + k0 + 9) * HID + n0));
        float4 va = __ldg((const float4*)(W2 + (size_t)k0       * HID + n0));
        float4 vb = __ldg((const float4*)(W2 + (size_t)(k0 + 1) * HID + n0));
        float4 vc = __ldg((const float4*)(W2 + (size_t)(k0 + 8) * HID + n0));
        float4 vd = __ldg((const float4*)(W2 + (size_t)(k0 + 9) * HID + n0));
        int slot = kt * 4 + tt;
        #pragma unroll
        for (int n = 0; n < 4; n++) {
            float a0 = (&wa.x)[n], b0 = (&wb.x)[n], c0 = (&wc.x)[n], d0 = (&wd.x)[n];
            float a2 = (&va.x)[n], b2v = (&vb.x)[n], c2 = (&vc.x)[n], d2 = (&vd.x)[n];
            sW1p[(n0 + n) * WPH + slot] = make_uint2(h2bits(a0, b0), h2bits(c0, d0));
            sW2p[(n0 + n) * WPH + slot] = make_uint2(h2bits(a2, b2v), h2bits(c2, d2));
        }
    }

    // ---- stage agg: 512 items, one per thread ----
    const float4* comb4 = (const float4*)combined;
    {
        int i = tid;                 // (node, kt)
        int n = i >> 2, kt = i & 3;
        int node = node0 + n;
        float4 f0 = make_float4(0.f,0.f,0.f,0.f), f1 = f0, f2 = f0, f3 = f0;
        if (node < N_NODES) {
            const float4* src = comb4 + (size_t)node * 32 + 16 + kt * 4;
            f0 = __ldg(src + 0); f1 = __ldg(src + 1);
            f2 = __ldg(src + 2); f3 = __ldg(src + 3);
        }
        uint32_t p0 = h2bits(f0.x, f0.y), p1 = h2bits(f0.z, f0.w);
        uint32_t p2 = h2bits(f1.x, f1.y), p3 = h2bits(f1.z, f1.w);
        uint32_t p4 = h2bits(f2.x, f2.y), p5 = h2bits(f2.z, f2.w);
        uint32_t p6 = h2bits(f3.x, f3.y), p7 = h2bits(f3.z, f3.w);
        uint4* dst = (uint4*)(sAp + n * APH + kt * 4);
        dst[0] = make_uint4(p0, p4, p1, p5);
        dst[1] = make_uint4(p2, p6, p3, p7);
    }

    int m0 = wm * 16;                  // warp's rows within the tile
    int rowA = node0 + m0 + g;
    int rowB = rowA + 8;
    bool okA = rowA < N_NODES;
    bool okB = rowB < N_NODES;

    // ---- layer 1 accumulators: D = t1 + agg @ W1b (4 nt = cols wn*32..) ----
    float d[4][4];
    #pragma unroll
    for (int nl = 0; nl < 4; nl++) {
        int nt = wn * 4 + nl;
        float2 vA = make_float2(0.f, 0.f), vB = make_float2(0.f, 0.f);
        if (okA) vA = *(const float2*)(d_t1 + (size_t)rowA * HID + nt * 8 + 2 * t);
        if (okB) vB = *(const float2*)(d_t1 + (size_t)rowB * HID + nt * 8 + 2 * t);
        d[nl][0] = vA.x; d[nl][1] = vA.y; d[nl][2] = vB.x; d[nl][3] = vB.y;
    }
    __syncthreads();

    // ---- layer 1 mainloop (4 kt-steps of K=16) ----
    #pragma unroll
    for (int kt = 0; kt < 4; kt++) {
        uint2 pA0 = sAp[(m0 + g)     * APH + kt * 4 + t];   // {a0, a2}
        uint2 pA1 = sAp[(m0 + g + 8) * APH + kt * 4 + t];   // {a1, a3}
        #pragma unroll
        for (int nl = 0; nl < 4; nl++) {
            int nt = wn * 4 + nl;
            uint2 b = sW1p[(nt * 8 + g) * WPH + kt * 4 + t];
            mma_f16(d[nl][0], d[nl][1], d[nl][2], d[nl][3],
                    pA0.x, pA1.x, pA0.y, pA1.y, b.x, b.y);
        }
    }
    __syncthreads();   // all layer-1 agg reads done before overwrite with h

    // ---- SiLU; store h into sAp (rows shared across warp pair) ----
    #pragma unroll
    for (int nl = 0; nl < 4; nl++) {
        int nt = wn * 4 + nl;
        float h0 = __fdividef(d[nl][0], 1.0f + __expf(-d[nl][0]));
        float h1 = __fdividef(d[nl][1], 1.0f + __expf(-d[nl][1]));
        float h2 = __fdividef(d[nl][2], 1.0f + __expf(-d[nl][2]));
        float h3 = __fdividef(d[nl][3], 1.0f + __expf(-d[nl][3]));
        int q = nt * 4 + t;
        int kt_h = q >> 3, r = q & 7;
        int word = 2 * (kt_h * 4 + (r & 3)) + (r >> 2);
        ((uint32_t*)(sAp + (m0 + g)     * APH))[word] = h2bits(h0, h1);
        ((uint32_t*)(sAp + (m0 + g + 8) * APH))[word] = h2bits(h2, h3);
    }
    __syncthreads();   // h complete (both col halves) before layer-2 reads

    // ---- layer 2: D = b2 + h @ W2 ----
    #pragma unroll
    for (int nl = 0; nl < 4; nl++) {
        int nt = wn * 4 + nl;
        float2 bb = *(const float2*)(b2 + nt * 8 + 2 * t);
        d[nl][0] = bb.x; d[nl][1] = bb.y; d[nl][2] = bb.x; d[nl][3] = bb.y;
    }

    #pragma unroll
    for (int kt = 0; kt < 4; kt++) {
        uint2 pA0 = sAp[(m0 + g)     * APH + kt * 4 + t];
        uint2 pA1 = sAp[(m0 + g + 8) * APH + kt * 4 + t];
        #pragma unroll
        for (int nl = 0; nl < 4; nl++) {
            int nt = wn * 4 + nl;
            uint2 b = sW2p[(nt * 8 + g) * WPH + kt * 4 + t];
            mma_f16(d[nl][0], d[nl][1], d[nl][2], d[nl][3],
                    pA0.x, pA1.x, pA0.y, pA1.y, b.x, b.y);
        }
    }

    // ---- write out ----
    #pragma unroll
    for (int nl = 0; nl < 4; nl++) {
        int nt = wn * 4 + nl;
        if (okA) {
            *(float2*)(out + (size_t)rowA * HID + nt * 8 + 2 * t)
                = make_float2(d[nl][0], d[nl][1]);
        }
        if (okB) {
            *(float2*)(out + (size_t)rowB * HID + nt * 8 + 2 * t)
                = make_float2(d[nl][2], d[nl][3]);
        }
    }
}

// ---------------------------------------------------------------------------
extern "C" void kernel_launch(void* const* d_in, const int* in_sizes, int n_in,
                              void* d_out, int out_size) {
    const int*   edge_index = (const int*)d_in[0];
    const float* edge_attr  = (const float*)d_in[1];
    const float* x          = (const float*)d_in[2];
    const float* W1         = (const float*)d_in[3];
    const float* b1         = (const float*)d_in[4];
    const float* W2         = (const float*)d_in[5];
    const float* b2         = (const float*)d_in[6];

    float* out      = (float*)d_out;
    float* combined = out + (size_t)N_NODES * HID;

    // contiguous memset of the whole combined region (fast DMA shape;
    // x half overwritten by K1's GEMM branch)
    cudaMemsetAsync(combined, 0, (size_t)N_NODES * CDIM * sizeof(float));

    // K1: scatter + t1 GEMM + x copy
    {
        int smem = (HID * HID) * 4 + NTILE * 16 * 16;
        cudaFuncSetAttribute(scatter_gemm_kernel,
                             cudaFuncAttributeMaxDynamicSharedMemorySize, smem);
        scatter_gemm_kernel<<<TOTAL_BLOCKS, 256, smem>>>(
            edge_index, (const float4*)edge_attr, (const float4*)x,
            W1, b1, combined);
    }

    // K2: tensor-core MLP (fp16 k16, 512 threads, N-split warp pairs)
    {
        int smem = (2 * HID * WPH + MT * APH) * (int)sizeof(uint2);   // 40 KB
        cudaFuncSetAttribute(mlp2_mma_kernel,
                             cudaFuncAttributeMaxDynamicSharedMemorySize, smem);
        mlp2_mma_kernel<<<M_BLOCKS, 512, smem>>>(combined, W1, W2, b2, out);
    }
}